// round 1
// baseline (speedup 1.0000x reference)
#include <cuda_runtime.h>
#include <cstdint>

#define NNODES 100000
#define NEDGES 1600000
#define FEATS  256
#define MAXK   32
#define KC     16   // K-chunk for GEMM

// ---------------- scratch (no allocations allowed) ----------------
__device__ float         g_val[NNODES * MAXK];
__device__ unsigned char g_col[NNODES * MAXK];
__device__ int           g_deg[NNODES];
__device__ int           g_off[NNODES + 1];
__device__ int           g_cur[NNODES];
__device__ int           g_csr[NEDGES];
__device__ int           g_is64;

// ---------------- dtype detection for src/dst ----------------
__global__ void k_detect(const void* src) {
    if (threadIdx.x == 0 && blockIdx.x == 0) {
        const long long* p = (const long long*)src;
        int ok = 1;
        for (int i = 0; i < 64; i++) {
            long long v = p[i];
            if (v < 0 || v >= NNODES) { ok = 0; break; }
        }
        g_is64 = ok;
    }
}

__device__ __forceinline__ int ld_idx(const void* p, int i) {
    if (g_is64) return (int)((const long long*)p)[i];
    return ((const int*)p)[i];
}

// ---------------- init ----------------
__global__ void k_zero_deg() {
    int i = blockIdx.x * blockDim.x + threadIdx.x;
    if (i < NNODES) g_deg[i] = 0;
}

// ---------------- degree count ----------------
__global__ void k_count(const void* dst) {
    int e = blockIdx.x * blockDim.x + threadIdx.x;
    if (e < NEDGES) atomicAdd(&g_deg[ld_idx(dst, e)], 1);
}

// ---------------- single-block exclusive scan ----------------
__global__ void k_scan() {
    __shared__ int sums[1024];
    const int CH = (NNODES + 1023) / 1024;   // 98
    int t = threadIdx.x;
    int b = t * CH;
    int s = 0;
    for (int i = 0; i < CH; i++) {
        int idx = b + i;
        if (idx < NNODES) s += g_deg[idx];
    }
    sums[t] = s;
    __syncthreads();
    // Hillis-Steele inclusive scan
    for (int off = 1; off < 1024; off <<= 1) {
        int x = (t >= off) ? sums[t - off] : 0;
        __syncthreads();
        sums[t] += x;
        __syncthreads();
    }
    int run = (t == 0) ? 0 : sums[t - 1];
    for (int i = 0; i < CH; i++) {
        int idx = b + i;
        if (idx < NNODES) {
            g_off[idx] = run;
            g_cur[idx] = run;
            run += g_deg[idx];
        }
    }
    if (t == 1023) g_off[NNODES] = sums[1023];
}

// ---------------- CSR scatter (edges grouped by dst) ----------------
__global__ void k_scatter(const void* src, const void* dst) {
    int e = blockIdx.x * blockDim.x + threadIdx.x;
    if (e < NEDGES) {
        int s = ld_idx(src, e);
        int d = ld_idx(dst, e);
        int pos = atomicAdd(&g_cur[d], 1);
        g_csr[pos] = s;
    }
}

// ---------------- fused dual GEMM + MaxK top-32 ----------------
// Block = 256 threads (8 warps). Tile = 32 rows x 256 cols.
// Warp w owns rows rowBase+4w..+3 entirely; lane owns cols {4*lane..+3, 128+4*lane..+3}.
__global__ __launch_bounds__(256) void k_gemm_topk(
    const float* __restrict__ feat,
    const float* __restrict__ Ws,
    const float* __restrict__ Wn,
    float* __restrict__ out)
{
    __shared__ float As[KC][36];          // [k][row], padded stride (16B-aligned for row%4==0)
    __shared__ float Bs[2][KC][256];      // [self/neigh][k][col]

    int t = threadIdx.x;
    int lane = t & 31;
    int w = t >> 5;
    int rowBase = blockIdx.x * 32;

    float accS[4][8];
    float accN[4][8];
#pragma unroll
    for (int i = 0; i < 4; i++)
#pragma unroll
        for (int j = 0; j < 8; j++) { accS[i][j] = 0.f; accN[i][j] = 0.f; }

    for (int kc = 0; kc < FEATS; kc += KC) {
        // A: 32 rows x KC -> 512 floats; each thread loads a float2
        {
            int r = t >> 3;
            int k0 = (t & 7) * 2;
            float2 v = *(const float2*)&feat[(size_t)(rowBase + r) * FEATS + kc + k0];
            As[k0][r] = v.x;
            As[k0 + 1][r] = v.y;
        }
        // B: 2 weights x KC x 256 = 8192 floats; each thread loads 8 float4s
#pragma unroll
        for (int m = 0; m < 2; m++) {
            const float* W = m ? Wn : Ws;
#pragma unroll
            for (int i = 0; i < 4; i++) {
                int lin = t + i * 256;          // float4 index 0..1023
                int k = lin >> 6;
                int c4 = lin & 63;
                *(float4*)&Bs[m][k][c4 * 4] =
                    *(const float4*)&W[(size_t)(kc + k) * FEATS + c4 * 4];
            }
        }
        __syncthreads();

#pragma unroll
        for (int k = 0; k < KC; k++) {
            float4 a4 = *(const float4*)&As[k][w * 4];
            float av[4] = { a4.x, a4.y, a4.z, a4.w };
            float4 s0 = *(const float4*)&Bs[0][k][lane * 4];
            float4 s1 = *(const float4*)&Bs[0][k][128 + lane * 4];
            float4 n0 = *(const float4*)&Bs[1][k][lane * 4];
            float4 n1 = *(const float4*)&Bs[1][k][128 + lane * 4];
            float bs[8] = { s0.x, s0.y, s0.z, s0.w, s1.x, s1.y, s1.z, s1.w };
            float bn[8] = { n0.x, n0.y, n0.z, n0.w, n1.x, n1.y, n1.z, n1.w };
#pragma unroll
            for (int i = 0; i < 4; i++) {
#pragma unroll
                for (int j = 0; j < 8; j++) {
                    accS[i][j] += av[i] * bs[j];
                    accN[i][j] += av[i] * bn[j];
                }
            }
        }
        __syncthreads();
    }

    // ---- epilogue 1: write h_self to d_out (it becomes the output base) ----
    int r0 = rowBase + w * 4;
#pragma unroll
    for (int i = 0; i < 4; i++) {
        float4 v0 = make_float4(accS[i][0], accS[i][1], accS[i][2], accS[i][3]);
        float4 v1 = make_float4(accS[i][4], accS[i][5], accS[i][6], accS[i][7]);
        *(float4*)&out[(size_t)(r0 + i) * FEATS + lane * 4]       = v0;
        *(float4*)&out[(size_t)(r0 + i) * FEATS + 128 + lane * 4] = v1;
    }

    // ---- epilogue 2: register-resident top-32 of each neigh row ----
    // key: monotone float bits, low byte replaced by (255-col). Unique per entry.
#pragma unroll
    for (int i = 0; i < 4; i++) {
        unsigned ck[8];
#pragma unroll
        for (int j = 0; j < 8; j++) {
            int col = (j < 4) ? (lane * 4 + j) : (128 + lane * 4 + (j - 4));
            unsigned u = __float_as_uint(accN[i][j]);
            unsigned key = (u & 0x80000000u) ? ~u : (u | 0x80000000u);
            ck[j] = (key & 0xFFFFFF00u) | (255u - (unsigned)col);
        }
        unsigned win = 0;
        for (int it = 0; it < MAXK; it++) {
            unsigned m = ck[0];
#pragma unroll
            for (int j = 1; j < 8; j++) m = (ck[j] > m) ? ck[j] : m;
#pragma unroll
            for (int off = 16; off > 0; off >>= 1) {
                unsigned o = __shfl_xor_sync(0xFFFFFFFFu, m, off);
                m = (o > m) ? o : m;
            }
            if (lane == it) win = m;
#pragma unroll
            for (int j = 0; j < 8; j++) if (ck[j] == m) ck[j] = 0;
        }
        // decode winner owned by this lane (iteration == lane)
        int col = 255 - (int)(win & 0xFFu);
        unsigned kk = win & 0xFFFFFF00u;
        unsigned u = (kk & 0x80000000u) ? (kk & 0x7FFFFFFFu) : ~kk;
        g_val[(size_t)(r0 + i) * MAXK + lane] = __uint_as_float(u);
        g_col[(size_t)(r0 + i) * MAXK + lane] = (unsigned char)col;
    }
}

// ---------------- aggregation: one warp per dst node ----------------
__global__ __launch_bounds__(256) void k_aggregate(float* __restrict__ out) {
    __shared__ float acc[8][256];
    int w = threadIdx.x >> 5;
    int lane = threadIdx.x & 31;
    int v = blockIdx.x * 8 + w;
    if (v >= NNODES) return;

#pragma unroll
    for (int j = 0; j < 8; j++) acc[w][lane + 32 * j] = 0.f;
    __syncwarp();

    int beg = g_off[v];
    int end = g_off[v + 1];
    for (int e = beg; e < end; e++) {
        int s = g_csr[e];
        int c = (int)g_col[(size_t)s * MAXK + lane];
        float val = g_val[(size_t)s * MAXK + lane];
        atomicAdd(&acc[w][c], val);   // cols distinct within one edge; atomics for cross-iter safety
    }
    __syncwarp();

    int deg = end - beg;
    float inv = 1.0f / (float)(deg > 0 ? deg : 1);
    size_t base = (size_t)v * FEATS;
#pragma unroll
    for (int j = 0; j < 8; j++) {
        int c = lane + 32 * j;
        out[base + c] += acc[w][c] * inv;   // out already holds h_self
    }
}

// ---------------- launch ----------------
extern "C" void kernel_launch(void* const* d_in, const int* in_sizes, int n_in,
                              void* d_out, int out_size) {
    const float* feat = (const float*)d_in[0];
    const float* Ws   = (const float*)d_in[1];
    const float* Wn   = (const float*)d_in[2];
    const void*  src  = d_in[3];
    const void*  dst  = d_in[4];
    float* out = (float*)d_out;

    k_detect<<<1, 64>>>(src);
    k_zero_deg<<<(NNODES + 255) / 256, 256>>>();
    k_count<<<(NEDGES + 255) / 256, 256>>>(dst);
    k_scan<<<1, 1024>>>();
    k_scatter<<<(NEDGES + 255) / 256, 256>>>(src, dst);
    k_gemm_topk<<<NNODES / 32, 256>>>(feat, Ws, Wn, out);
    k_aggregate<<<(NNODES + 7) / 8, 256>>>(out);
}

// round 3
// speedup vs baseline: 1.1217x; 1.1217x over previous
#include <cuda_runtime.h>
#include <cuda_bf16.h>
#include <cstdint>

#define NNODES 100000
#define NPAD   100096        // 782 * 128
#define NEDGES 1600000
#define FEATS  256
#define MAXK   32
#define NCHUNK 8             // 256 / 32
#define AP     80            // padded smem row stride (bytes) for 32 bf16
#define SSZ    40960         // per-stage smem: Ahi|Alo|Bhi|Blo planes of 10240B

// ---------------- scratch (no allocations allowed) ----------------
__device__ float           g_val[NNODES * MAXK];
__device__ unsigned char   g_col[NNODES * MAXK];
__device__ int             g_deg[NNODES];
__device__ int             g_off[NNODES + 1];
__device__ int             g_cur[NNODES];
__device__ int             g_csr[NEDGES];
__device__ int             g_is64;
__device__ int             g_bsum[128];
__device__ int             g_bpre[128];
__device__ __nv_bfloat16   g_ahi[(size_t)NPAD * 256];
__device__ __nv_bfloat16   g_alo[(size_t)NPAD * 256];
__device__ __nv_bfloat16   g_bhi[512 * 256];          // [n 0..511][k] = W^T, n<256 self, n>=256 neigh
__device__ __nv_bfloat16   g_blo[512 * 256];
__device__ float           g_neigh[(size_t)NPAD * 256];

// ---------------- helpers ----------------
__device__ __forceinline__ uint32_t smem_u32(const void* p) {
    uint32_t a;
    asm("{ .reg .u64 t; cvta.to.shared.u64 t, %1; cvt.u32.u64 %0, t; }" : "=r"(a) : "l"(p));
    return a;
}
__device__ __forceinline__ void cp16(uint32_t dst, const void* src) {
    asm volatile("cp.async.cg.shared.global [%0], [%1], 16;" :: "r"(dst), "l"(src));
}
#define CP_COMMIT() asm volatile("cp.async.commit_group;" ::: "memory")
#define CP_WAIT(n)  asm volatile("cp.async.wait_group %0;" :: "n"(n) : "memory")

__device__ __forceinline__ void ldm4(uint32_t r[4], uint32_t addr) {
    asm volatile("ldmatrix.sync.aligned.m8n8.x4.shared.b16 {%0,%1,%2,%3}, [%4];"
                 : "=r"(r[0]), "=r"(r[1]), "=r"(r[2]), "=r"(r[3]) : "r"(addr));
}
__device__ __forceinline__ void mma_bf16(float* c, const uint32_t* a, const uint32_t* b) {
    asm volatile("mma.sync.aligned.m16n8k16.row.col.f32.bf16.bf16.f32 "
                 "{%0,%1,%2,%3}, {%4,%5,%6,%7}, {%8,%9}, {%0,%1,%2,%3};"
                 : "+f"(c[0]), "+f"(c[1]), "+f"(c[2]), "+f"(c[3])
                 : "r"(a[0]), "r"(a[1]), "r"(a[2]), "r"(a[3]), "r"(b[0]), "r"(b[1]));
}
__device__ __forceinline__ uint32_t pack2(float x, float y) {
    uint32_t lo = (uint32_t)__bfloat16_as_ushort(__float2bfloat16_rn(x));
    uint32_t hi = (uint32_t)__bfloat16_as_ushort(__float2bfloat16_rn(y));
    return lo | (hi << 16);
}

// ---------------- dtype detection for src/dst ----------------
__global__ void k_detect(const void* src) {
    if (threadIdx.x == 0 && blockIdx.x == 0) {
        const long long* p = (const long long*)src;
        int ok = 1;
        for (int i = 0; i < 64; i++) {
            long long v = p[i];
            if (v < 0 || v >= NNODES) { ok = 0; break; }
        }
        g_is64 = ok;
    }
}
__device__ __forceinline__ int ld_idx(const void* p, int i) {
    if (g_is64) return (int)((const long long*)p)[i];
    return ((const int*)p)[i];
}

// ---------------- weight prep: W^T + bf16 hi/lo split ----------------
__global__ void k_prep_w(const float* __restrict__ Ws, const float* __restrict__ Wn) {
    int i = blockIdx.x * 256 + threadIdx.x;   // i = n*256 + k
    if (i >= 512 * 256) return;
    int k = i & 255;
    int n = i >> 8;                            // 0..511
    float x = (n >= 256) ? Wn[k * 256 + (n - 256)] : Ws[k * 256 + n];
    __nv_bfloat16 h = __float2bfloat16_rn(x);
    float l = x - __bfloat162float(h);
    g_bhi[i] = h;
    g_blo[i] = __float2bfloat16_rn(l);
}

// ---------------- A prep: bf16 hi/lo split, zero-padded rows ----------------
__global__ void k_prep_a(const float* __restrict__ feat) {
    int i = blockIdx.x * 256 + threadIdx.x;    // one float4 per thread
    if (i >= NPAD * 64) return;
    int row = i >> 6;
    int col = (i & 63) * 4;
    float4 v = (row < NNODES) ? *(const float4*)&feat[(size_t)row * 256 + col]
                              : make_float4(0.f, 0.f, 0.f, 0.f);
    float xs[4] = { v.x, v.y, v.z, v.w };
    float hs[4], ls[4];
#pragma unroll
    for (int q = 0; q < 4; q++) {
        __nv_bfloat16 h = __float2bfloat16_rn(xs[q]);
        hs[q] = __bfloat162float(h);
        ls[q] = xs[q] - hs[q];
    }
    size_t o = (size_t)row * 256 + col;
    *(uint2*)&g_ahi[o] = make_uint2(pack2(hs[0], hs[1]), pack2(hs[2], hs[3]));
    *(uint2*)&g_alo[o] = make_uint2(pack2(ls[0], ls[1]), pack2(ls[2], ls[3]));
}

// ---------------- init / degree / scan / scatter ----------------
__global__ void k_zero_deg() {
    int i = blockIdx.x * blockDim.x + threadIdx.x;
    if (i < NNODES) g_deg[i] = 0;
}
__global__ void k_count(const void* dst) {
    int e = blockIdx.x * blockDim.x + threadIdx.x;
    if (e < NEDGES) atomicAdd(&g_deg[ld_idx(dst, e)], 1);
}
__global__ void k_scan1() {
    __shared__ int sh[1024];
    int t = threadIdx.x;
    int i = blockIdx.x * 1024 + t;
    int v = (i < NNODES) ? g_deg[i] : 0;
    sh[t] = v; __syncthreads();
    for (int off = 1; off < 1024; off <<= 1) {
        int x = (t >= off) ? sh[t - off] : 0;
        __syncthreads();
        sh[t] += x;
        __syncthreads();
    }
    if (i < NNODES) g_off[i] = sh[t] - v;
    if (t == 1023) g_bsum[blockIdx.x] = sh[1023];
}
__global__ void k_scan2() {
    __shared__ int sh[128];
    int t = threadIdx.x;
    int v = (t < 98) ? g_bsum[t] : 0;
    sh[t] = v; __syncthreads();
    for (int off = 1; off < 128; off <<= 1) {
        int x = (t >= off) ? sh[t - off] : 0;
        __syncthreads();
        sh[t] += x;
        __syncthreads();
    }
    g_bpre[t] = sh[t] - v;
    if (t == 127) g_off[NNODES] = sh[127];
}
__global__ void k_scan3() {
    int i = blockIdx.x * 1024 + threadIdx.x;
    if (i < NNODES) {
        int o = g_off[i] + g_bpre[blockIdx.x];
        g_off[i] = o;
        g_cur[i] = o;
    }
}
__global__ void k_scatter(const void* src, const void* dst) {
    int e = blockIdx.x * blockDim.x + threadIdx.x;
    if (e < NEDGES) {
        int s = ld_idx(src, e);
        int d = ld_idx(dst, e);
        int pos = atomicAdd(&g_cur[d], 1);
        g_csr[pos] = s;
    }
}

// ---------------- bf16x2 mma.sync GEMM: C[NPAD x 512] ----------------
// grid (4 nblocks, 782 rowblocks). CTA 128x128, 8 warps (4M x 2N), warp 32x64.
// 3-term compensated: Ahi*Bhi + Ahi*Blo + Alo*Bhi.
__global__ __launch_bounds__(256, 1) void k_gemm(float* __restrict__ out) {
    extern __shared__ char sm[];
    uint32_t sb = smem_u32(sm);
    int t = threadIdx.x, lane = t & 31, w = t >> 5;
    int nb = blockIdx.x, rb = blockIdx.y;
    int warpM = w & 3, warpN = w >> 2;
    int rowBase = rb * 128;

    auto issue = [&](int stage, int chunk) {
        uint32_t st = sb + stage * SSZ;
        int kc = chunk * 32;
#pragma unroll
        for (int i = 0; i < 2; i++) {
            int idx = t * 2 + i;            // 0..511
            int row = idx >> 2, seg = idx & 3;
            uint32_t dof = (uint32_t)(row * AP + seg * 16);
            size_t ao = (size_t)(rowBase + row) * 256 + kc + seg * 8;
            size_t bo = (size_t)(nb * 128 + row) * 256 + kc + seg * 8;
            cp16(st + dof,         &g_ahi[ao]);
            cp16(st + 10240 + dof, &g_alo[ao]);
            cp16(st + 20480 + dof, &g_bhi[bo]);
            cp16(st + 30720 + dof, &g_blo[bo]);
        }
        CP_COMMIT();
    };

    float acc[2][8][4];
#pragma unroll
    for (int mf = 0; mf < 2; mf++)
#pragma unroll
        for (int nf = 0; nf < 8; nf++)
#pragma unroll
            for (int q = 0; q < 4; q++) acc[mf][nf][q] = 0.f;

    issue(0, 0);
    issue(1, 1);

    // per-lane ldmatrix address offsets (within plane)
    uint32_t aoff = (uint32_t)((lane & 7) + ((lane & 8) ? 8 : 0)) * AP + ((lane & 16) ? 16 : 0);
    uint32_t boff = (uint32_t)((lane & 7) + ((lane & 16) ? 8 : 0)) * AP + ((lane & 8) ? 16 : 0);

    for (int c = 0; c < NCHUNK; c++) {
        if (c + 1 < NCHUNK) { CP_WAIT(1); } else { CP_WAIT(0); }
        __syncthreads();

        uint32_t st = sb + (c & 1) * SSZ;
#pragma unroll
        for (int ks = 0; ks < 2; ks++) {
            uint32_t ah[2][4], al[2][4], bh[8][2], bl[8][2];
#pragma unroll
            for (int mf = 0; mf < 2; mf++) {
                uint32_t ra = st + (uint32_t)(warpM * 32 + mf * 16) * AP + aoff + ks * 32;
                ldm4(ah[mf], ra);
                ldm4(al[mf], ra + 10240);
            }
#pragma unroll
            for (int p = 0; p < 4; p++) {
                uint32_t rbn = st + 20480 + (uint32_t)(warpN * 64 + p * 16) * AP + boff + ks * 32;
                uint32_t r[4];
                ldm4(r, rbn);
                bh[2*p][0] = r[0]; bh[2*p][1] = r[1];
                bh[2*p+1][0] = r[2]; bh[2*p+1][1] = r[3];
                ldm4(r, rbn + 10240);
                bl[2*p][0] = r[0]; bl[2*p][1] = r[1];
                bl[2*p+1][0] = r[2]; bl[2*p+1][1] = r[3];
            }
#pragma unroll
            for (int mf = 0; mf < 2; mf++)
#pragma unroll
                for (int nf = 0; nf < 8; nf++) {
                    mma_bf16(acc[mf][nf], ah[mf], bh[nf]);
                    mma_bf16(acc[mf][nf], ah[mf], bl[nf]);
                    mma_bf16(acc[mf][nf], al[mf], bh[nf]);
                }
        }

        if (c + 2 < NCHUNK) {
            __syncthreads();
            issue(c & 1, c + 2);
        }
    }

    // epilogue
    int g = lane >> 2, tt = lane & 3;
    bool selfSide = (nb < 2);
#pragma unroll
    for (int mf = 0; mf < 2; mf++) {
#pragma unroll
        for (int nf = 0; nf < 8; nf++) {
            int row0 = rowBase + warpM * 32 + mf * 16 + g;
            int col = nb * 128 + warpN * 64 + nf * 8 + tt * 2;
            float2 v0 = make_float2(acc[mf][nf][0], acc[mf][nf][1]);
            float2 v1 = make_float2(acc[mf][nf][2], acc[mf][nf][3]);
            if (selfSide) {
                if (row0 < NNODES)     *(float2*)&out[(size_t)row0 * 256 + col] = v0;
                if (row0 + 8 < NNODES) *(float2*)&out[(size_t)(row0 + 8) * 256 + col] = v1;
            } else {
                int nc = col - 256;
                if (row0 < NNODES)     *(float2*)&g_neigh[(size_t)row0 * 256 + nc] = v0;
                if (row0 + 8 < NNODES) *(float2*)&g_neigh[(size_t)(row0 + 8) * 256 + nc] = v1;
            }
        }
    }
}

// ---------------- top-32 per row (warp per row), exact values ----------------
__global__ __launch_bounds__(256) void k_topk() {
    __shared__ float smr[8][257];
    int w = threadIdx.x >> 5, lane = threadIdx.x & 31;
    int row = blockIdx.x * 8 + w;
    if (row >= NNODES) return;

    unsigned ck[8];
#pragma unroll
    for (int j = 0; j < 8; j++) {
        int col = j * 32 + lane;
        float v = g_neigh[(size_t)row * 256 + col];
        smr[w][col] = v;
        unsigned u = __float_as_uint(v);
        unsigned key = (u & 0x80000000u) ? ~u : (u | 0x80000000u);
        ck[j] = (key & 0xFFFFFF00u) | (255u - (unsigned)col);
    }
    __syncwarp();

    unsigned win = 0;
    for (int it = 0; it < MAXK; it++) {
        unsigned mx = ck[0];
#pragma unroll
        for (int j = 1; j < 8; j++) mx = (ck[j] > mx) ? ck[j] : mx;
#pragma unroll
        for (int off = 16; off > 0; off >>= 1) {
            unsigned o = __shfl_xor_sync(0xFFFFFFFFu, mx, off);
            mx = (o > mx) ? o : mx;
        }
        if (lane == it) win = mx;
#pragma unroll
        for (int j = 0; j < 8; j++) if (ck[j] == mx) ck[j] = 0;
    }
    int col = 255 - (int)(win & 0xFFu);
    g_val[(size_t)row * MAXK + lane] = smr[w][col];   // exact value
    g_col[(size_t)row * MAXK + lane] = (unsigned char)col;
}

// ---------------- aggregation: one warp per dst node ----------------
__global__ __launch_bounds__(256) void k_aggregate(float* __restrict__ out) {
    __shared__ float acc[8][256];
    int w = threadIdx.x >> 5;
    int lane = threadIdx.x & 31;
    int v = blockIdx.x * 8 + w;
    if (v >= NNODES) return;

#pragma unroll
    for (int j = 0; j < 8; j++) acc[w][lane + 32 * j] = 0.f;
    __syncwarp();

    int beg = g_off[v];
    int end = g_off[v + 1];
    for (int e = beg; e < end; e++) {
        int s = g_csr[e];
        int c = (int)g_col[(size_t)s * MAXK + lane];
        float val = g_val[(size_t)s * MAXK + lane];
        atomicAdd(&acc[w][c], val);
    }
    __syncwarp();

    int deg = end - beg;
    float inv = 1.0f / (float)(deg > 0 ? deg : 1);
    size_t bo = (size_t)v * FEATS;
#pragma unroll
    for (int j = 0; j < 8; j++) {
        int c = lane + 32 * j;
        out[bo + c] += acc[w][c] * inv;
    }
}

// ---------------- launch ----------------
extern "C" void kernel_launch(void* const* d_in, const int* in_sizes, int n_in,
                              void* d_out, int out_size) {
    const float* feat = (const float*)d_in[0];
    const float* Ws   = (const float*)d_in[1];
    const float* Wn   = (const float*)d_in[2];
    const void*  src  = d_in[3];
    const void*  dst  = d_in[4];
    float* out = (float*)d_out;

    cudaFuncSetAttribute(k_gemm, cudaFuncAttributeMaxDynamicSharedMemorySize, 2 * SSZ);

    k_prep_w<<<512, 256>>>(Ws, Wn);
    k_prep_a<<<(NPAD * 64 + 255) / 256, 256>>>(feat);
    k_detect<<<1, 64>>>(src);
    k_zero_deg<<<(NNODES + 255) / 256, 256>>>();
    k_count<<<(NEDGES + 255) / 256, 256>>>(dst);
    k_scan1<<<98, 1024>>>();
    k_scan2<<<1, 128>>>();
    k_scan3<<<98, 1024>>>();
    k_scatter<<<(NEDGES + 255) / 256, 256>>>(src, dst);
    dim3 gg(4, 782);
    k_gemm<<<gg, 256, 2 * SSZ>>>(out);
    k_topk<<<(NNODES + 7) / 8, 256>>>();
    k_aggregate<<<(NNODES + 7) / 8, 256>>>(out);
}

// round 4
// speedup vs baseline: 1.3629x; 1.2150x over previous
#include <cuda_runtime.h>
#include <cuda_bf16.h>
#include <cstdint>

#define NNODES 100000
#define NEDGES 1600000
#define FEATS  256
#define MAXK   32
#define NCHUNK 8             // 256 / 32
#define AP     80            // padded smem row stride (bytes) for 32 bf16
#define APB    20480         // B plane bytes: 256 rows * AP
#define APA    10240         // A plane bytes: 128 rows * AP
#define SSZ    61440         // stage: Ahi|Alo (10240 ea) + Bhi|Blo (20480 ea)
#define NSTG   3
#define SMEM_DYN 184320      // 3 stages (epilogue overlay 128*258*4=132096 fits)

// ---------------- scratch (no allocations allowed) ----------------
__device__ float           g_val[NNODES * MAXK];
__device__ unsigned char   g_col[NNODES * MAXK];
__device__ int             g_deg[NNODES];
__device__ int             g_off[NNODES + 1];
__device__ int             g_cur[NNODES];
__device__ int             g_csr[NEDGES];
__device__ int             g_is64;
__device__ int             g_bsum[128];
__device__ int             g_bpre[128];
__device__ __nv_bfloat16   g_bhi[512 * 256];   // [n 0..511][k] = W^T; n<256 self, n>=256 neigh
__device__ __nv_bfloat16   g_blo[512 * 256];

// ---------------- helpers ----------------
__device__ __forceinline__ uint32_t smem_u32(const void* p) {
    uint32_t a;
    asm("{ .reg .u64 t; cvta.to.shared.u64 t, %1; cvt.u32.u64 %0, t; }" : "=r"(a) : "l"(p));
    return a;
}
__device__ __forceinline__ void cp16(uint32_t dst, const void* src) {
    asm volatile("cp.async.cg.shared.global [%0], [%1], 16;" :: "r"(dst), "l"(src));
}
#define CP_COMMIT() asm volatile("cp.async.commit_group;" ::: "memory")
#define CP_WAIT(n)  asm volatile("cp.async.wait_group %0;" :: "n"(n) : "memory")

__device__ __forceinline__ void ldm4(uint32_t r[4], uint32_t addr) {
    asm volatile("ldmatrix.sync.aligned.m8n8.x4.shared.b16 {%0,%1,%2,%3}, [%4];"
                 : "=r"(r[0]), "=r"(r[1]), "=r"(r[2]), "=r"(r[3]) : "r"(addr));
}
__device__ __forceinline__ void mma_bf16(float* c, const uint32_t* a, const uint32_t* b) {
    asm volatile("mma.sync.aligned.m16n8k16.row.col.f32.bf16.bf16.f32 "
                 "{%0,%1,%2,%3}, {%4,%5,%6,%7}, {%8,%9}, {%0,%1,%2,%3};"
                 : "+f"(c[0]), "+f"(c[1]), "+f"(c[2]), "+f"(c[3])
                 : "r"(a[0]), "r"(a[1]), "r"(a[2]), "r"(a[3]), "r"(b[0]), "r"(b[1]));
}
__device__ __forceinline__ uint32_t pack2(float x, float y) {
    uint32_t lo = (uint32_t)__bfloat16_as_ushort(__float2bfloat16_rn(x));
    uint32_t hi = (uint32_t)__bfloat16_as_ushort(__float2bfloat16_rn(y));
    return lo | (hi << 16);
}

// ---------------- dtype detection for src/dst ----------------
__global__ void k_detect(const void* src) {
    if (threadIdx.x == 0 && blockIdx.x == 0) {
        const long long* p = (const long long*)src;
        int ok = 1;
        for (int i = 0; i < 64; i++) {
            long long v = p[i];
            if (v < 0 || v >= NNODES) { ok = 0; break; }
        }
        g_is64 = ok;
    }
}
__device__ __forceinline__ int ld_idx(const void* p, int i) {
    if (g_is64) return (int)((const long long*)p)[i];
    return ((const int*)p)[i];
}

// ---------------- weight prep: W^T + bf16 hi/lo split ----------------
__global__ void k_prep_w(const float* __restrict__ Ws, const float* __restrict__ Wn) {
    int i = blockIdx.x * 256 + threadIdx.x;   // i = n*256 + k
    if (i >= 512 * 256) return;
    int k = i & 255;
    int n = i >> 8;
    float x = (n >= 256) ? Wn[k * 256 + (n - 256)] : Ws[k * 256 + n];
    __nv_bfloat16 h = __float2bfloat16_rn(x);
    float l = x - __bfloat162float(h);
    g_bhi[i] = h;
    g_blo[i] = __float2bfloat16_rn(l);
}

// ---------------- init / degree / scan / scatter ----------------
__global__ void k_zero_deg() {
    int i = blockIdx.x * blockDim.x + threadIdx.x;
    if (i < NNODES) g_deg[i] = 0;
}
__global__ void k_count(const void* dst) {
    int e = blockIdx.x * blockDim.x + threadIdx.x;
    if (e < NEDGES) atomicAdd(&g_deg[ld_idx(dst, e)], 1);
}
__global__ void k_scan1() {
    __shared__ int sh[1024];
    int t = threadIdx.x;
    int i = blockIdx.x * 1024 + t;
    int v = (i < NNODES) ? g_deg[i] : 0;
    sh[t] = v; __syncthreads();
    for (int off = 1; off < 1024; off <<= 1) {
        int x = (t >= off) ? sh[t - off] : 0;
        __syncthreads();
        sh[t] += x;
        __syncthreads();
    }
    if (i < NNODES) g_off[i] = sh[t] - v;
    if (t == 1023) g_bsum[blockIdx.x] = sh[1023];
}
__global__ void k_scan2() {
    __shared__ int sh[128];
    int t = threadIdx.x;
    int v = (t < 98) ? g_bsum[t] : 0;
    sh[t] = v; __syncthreads();
    for (int off = 1; off < 128; off <<= 1) {
        int x = (t >= off) ? sh[t - off] : 0;
        __syncthreads();
        sh[t] += x;
        __syncthreads();
    }
    g_bpre[t] = sh[t] - v;
    if (t == 127) g_off[NNODES] = sh[127];
}
__global__ void k_scan3() {
    int i = blockIdx.x * 1024 + threadIdx.x;
    if (i < NNODES) {
        int o = g_off[i] + g_bpre[blockIdx.x];
        g_off[i] = o;
        g_cur[i] = o;
    }
}
__global__ void k_scatter(const void* src, const void* dst) {
    int e = blockIdx.x * blockDim.x + threadIdx.x;
    if (e < NEDGES) {
        int s = ld_idx(src, e);
        int d = ld_idx(dst, e);
        int pos = atomicAdd(&g_cur[d], 1);
        g_csr[pos] = s;
    }
}

// ---------------- fused GEMM (+topk for neigh): C[128 x 256] per CTA ----------------
// grid (782, 2): y=0 -> h_self -> out; y=1 -> h_neigh -> in-place top-32 -> g_val/g_col.
// 8 warps: warpM = w&3 (32 rows), warpN = w>>2 (128 cols). 3-term bf16 compensation.
// A converted fp32->bf16 hi/lo in-kernel (register prefetch), B via 3-stage cp.async.
__global__ __launch_bounds__(256, 1) void k_gemm(const float* __restrict__ feat,
                                                 float* __restrict__ out) {
    extern __shared__ char sm[];
    uint32_t sb = smem_u32(sm);
    int t = threadIdx.x, lane = t & 31, w = t >> 5;
    int m = blockIdx.y;
    int rowBase = blockIdx.x * 128;
    int warpM = w & 3, warpN = w >> 2;

    // A register prefetch: row = t>>1, 16 cols at (t&1)*16
    int ar = t >> 1;
    int ah16 = (t & 1);
    int grA = rowBase + ar;
    bool aOK = grA < NNODES;
    const float* aRow = feat + (size_t)grA * FEATS + ah16 * 16;
    float aR[16];

    auto ldA = [&](int chunk) {
#pragma unroll
        for (int q = 0; q < 4; q++) {
            float4 v = aOK ? *(const float4*)(aRow + chunk * 32 + q * 4)
                           : make_float4(0.f, 0.f, 0.f, 0.f);
            aR[q*4+0] = v.x; aR[q*4+1] = v.y; aR[q*4+2] = v.z; aR[q*4+3] = v.w;
        }
    };
    auto stA = [&](int stage) {
        uint32_t st = sb + stage * SSZ;
        float hs[16];
#pragma unroll
        for (int q = 0; q < 16; q++) hs[q] = __bfloat162float(__float2bfloat16_rn(aR[q]));
#pragma unroll
        for (int s = 0; s < 2; s++) {       // two 16B segs (8 bf16 each)
            uint32_t hofs[4], lofs[4];
#pragma unroll
            for (int p = 0; p < 4; p++) {
                int q = s * 8 + p * 2;
                hofs[p] = pack2(hs[q], hs[q+1]);
                lofs[p] = pack2(aR[q] - hs[q], aR[q+1] - hs[q+1]);
            }
            uint32_t dof = (uint32_t)(ar * AP + (ah16 * 2 + s) * 16);
            *(uint4*)(sm + (st - smem_u32(sm)) + dof) = make_uint4(hofs[0], hofs[1], hofs[2], hofs[3]);
            *(uint4*)(sm + (st - smem_u32(sm)) + APA + dof) = make_uint4(lofs[0], lofs[1], lofs[2], lofs[3]);
        }
    };
    auto cpB = [&](int stage, int chunk) {
        uint32_t bh = sb + stage * SSZ + 2 * APA;
        uint32_t bl = bh + APB;
        int kc = chunk * 32;
#pragma unroll
        for (int i = 0; i < 4; i++) {
            int lin = t + i * 256;          // 0..1023: row = lin>>2, seg = lin&3
            int n = lin >> 2, seg = lin & 3;
            uint32_t dof = (uint32_t)(n * AP + seg * 16);
            size_t bo = (size_t)(m * 256 + n) * 256 + kc + seg * 8;
            cp16(bh + dof, &g_bhi[bo]);
            cp16(bl + dof, &g_blo[bo]);
        }
        CP_COMMIT();
    };

    float acc[2][16][4];
#pragma unroll
    for (int mf = 0; mf < 2; mf++)
#pragma unroll
        for (int nf = 0; nf < 16; nf++)
#pragma unroll
            for (int q = 0; q < 4; q++) acc[mf][nf][q] = 0.f;

    // prologue
    ldA(0); stA(0); cpB(0, 0);
    ldA(1); stA(1); cpB(1, 1);
    ldA(2);

    uint32_t aoff = (uint32_t)((lane & 7) + ((lane & 8) ? 8 : 0)) * AP + ((lane & 16) ? 16 : 0);
    uint32_t boff = (uint32_t)((lane & 7) + ((lane & 16) ? 8 : 0)) * AP + ((lane & 8) ? 16 : 0);

    for (int c = 0; c < NCHUNK; c++) {
        CP_WAIT(1);
        __syncthreads();

        if (c + 2 < NCHUNK) {
            stA((c + 2) % NSTG);            // from aR (chunk c+2)
            cpB((c + 2) % NSTG, c + 2);
            if (c + 3 < NCHUNK) ldA(c + 3);
        }

        uint32_t st = sb + (c % NSTG) * SSZ;
#pragma unroll
        for (int ks = 0; ks < 2; ks++) {
            uint32_t ahf[2][4], alf[2][4];
#pragma unroll
            for (int mf = 0; mf < 2; mf++) {
                uint32_t ra = st + (uint32_t)(warpM * 32 + mf * 16) * AP + aoff + ks * 32;
                ldm4(ahf[mf], ra);
                ldm4(alf[mf], ra + APA);
            }
#pragma unroll
            for (int p = 0; p < 8; p++) {
                uint32_t rbn = st + 2 * APA + (uint32_t)(warpN * 128 + p * 16) * AP + boff + ks * 32;
                uint32_t rh[4], rl[4];
                ldm4(rh, rbn);
                ldm4(rl, rbn + APB);
                uint32_t bh0[2] = { rh[0], rh[1] }, bh1[2] = { rh[2], rh[3] };
                uint32_t bl0[2] = { rl[0], rl[1] }, bl1[2] = { rl[2], rl[3] };
#pragma unroll
                for (int mf = 0; mf < 2; mf++) {
                    mma_bf16(acc[mf][2*p],   ahf[mf], bh0);
                    mma_bf16(acc[mf][2*p],   ahf[mf], bl0);
                    mma_bf16(acc[mf][2*p],   alf[mf], bh0);
                    mma_bf16(acc[mf][2*p+1], ahf[mf], bh1);
                    mma_bf16(acc[mf][2*p+1], ahf[mf], bl1);
                    mma_bf16(acc[mf][2*p+1], alf[mf], bh1);
                }
            }
        }
    }
    CP_WAIT(0);

    int g = lane >> 2, tt = lane & 3;
    if (m == 0) {
        // h_self straight to out
#pragma unroll
        for (int mf = 0; mf < 2; mf++)
#pragma unroll
            for (int nf = 0; nf < 16; nf++) {
                int r0 = rowBase + warpM * 32 + mf * 16 + g;
                int col = warpN * 128 + nf * 8 + tt * 2;
                if (r0 < NNODES)
                    *(float2*)&out[(size_t)r0 * 256 + col] = make_float2(acc[mf][nf][0], acc[mf][nf][1]);
                if (r0 + 8 < NNODES)
                    *(float2*)&out[(size_t)(r0 + 8) * 256 + col] = make_float2(acc[mf][nf][2], acc[mf][nf][3]);
            }
        return;
    }

    // h_neigh: stage into smem overlay, then in-CTA warp top-32
    __syncthreads();                         // everyone past pipeline reads
    float* stg = (float*)sm;                 // 128 rows x stride 258 floats
#pragma unroll
    for (int mf = 0; mf < 2; mf++)
#pragma unroll
        for (int nf = 0; nf < 16; nf++) {
            int lr = warpM * 32 + mf * 16 + g;
            int col = warpN * 128 + nf * 8 + tt * 2;
            *(float2*)&stg[(size_t)lr * 258 + col]       = make_float2(acc[mf][nf][0], acc[mf][nf][1]);
            *(float2*)&stg[(size_t)(lr + 8) * 258 + col] = make_float2(acc[mf][nf][2], acc[mf][nf][3]);
        }
    __syncthreads();

    for (int rr = 0; rr < 16; rr++) {
        int lr = w * 16 + rr;
        int grow = rowBase + lr;
        unsigned ck[8];
#pragma unroll
        for (int j = 0; j < 8; j++) {
            int col = j * 32 + lane;
            unsigned u = __float_as_uint(stg[(size_t)lr * 258 + col]);
            unsigned key = (u & 0x80000000u) ? ~u : (u | 0x80000000u);
            ck[j] = (key & 0xFFFFFF00u) | (255u - (unsigned)col);
        }
        unsigned win = 0;
        for (int it = 0; it < MAXK; it++) {
            unsigned mx = ck[0];
#pragma unroll
            for (int j = 1; j < 8; j++) mx = (ck[j] > mx) ? ck[j] : mx;
#pragma unroll
            for (int off = 16; off > 0; off >>= 1) {
                unsigned o = __shfl_xor_sync(0xFFFFFFFFu, mx, off);
                mx = (o > mx) ? o : mx;
            }
            if (lane == it) win = mx;
#pragma unroll
            for (int j = 0; j < 8; j++) if (ck[j] == mx) ck[j] = 0;
        }
        if (grow < NNODES) {
            int col = 255 - (int)(win & 0xFFu);
            g_val[(size_t)grow * MAXK + lane] = stg[(size_t)lr * 258 + col];  // exact
            g_col[(size_t)grow * MAXK + lane] = (unsigned char)col;
        }
    }
}

// ---------------- aggregation: one warp per dst node ----------------
__global__ __launch_bounds__(256) void k_aggregate(float* __restrict__ out) {
    __shared__ float acc[8][256];
    int w = threadIdx.x >> 5;
    int lane = threadIdx.x & 31;
    int v = blockIdx.x * 8 + w;
    if (v >= NNODES) return;

#pragma unroll
    for (int j = 0; j < 8; j++) acc[w][lane + 32 * j] = 0.f;
    __syncwarp();

    int beg = g_off[v];
    int end = g_off[v + 1];
    for (int e = beg; e < end; e++) {
        int s = g_csr[e];
        int c = (int)g_col[(size_t)s * MAXK + lane];
        float val = g_val[(size_t)s * MAXK + lane];
        atomicAdd(&acc[w][c], val);
    }
    __syncwarp();

    int deg = end - beg;
    float inv = 1.0f / (float)(deg > 0 ? deg : 1);
    size_t bo = (size_t)v * FEATS;
#pragma unroll
    for (int j = 0; j < 8; j++) {
        int c = lane + 32 * j;
        out[bo + c] += acc[w][c] * inv;
    }
}

// ---------------- launch (k_gemm is the 4th launch -> gets profiled) ----------------
extern "C" void kernel_launch(void* const* d_in, const int* in_sizes, int n_in,
                              void* d_out, int out_size) {
    const float* feat = (const float*)d_in[0];
    const float* Ws   = (const float*)d_in[1];
    const float* Wn   = (const float*)d_in[2];
    const void*  src  = d_in[3];
    const void*  dst  = d_in[4];
    float* out = (float*)d_out;

    cudaFuncSetAttribute(k_gemm, cudaFuncAttributeMaxDynamicSharedMemorySize, SMEM_DYN);

    k_prep_w<<<512, 256>>>(Ws, Wn);
    k_detect<<<1, 64>>>(src);
    k_zero_deg<<<(NNODES + 255) / 256, 256>>>();
    dim3 gg(782, 2);
    k_gemm<<<gg, 256, SMEM_DYN>>>(feat, out);     // 4th launch
    k_count<<<(NEDGES + 255) / 256, 256>>>(dst);
    k_scan1<<<98, 1024>>>();
    k_scan2<<<1, 128>>>();
    k_scan3<<<98, 1024>>>();
    k_scatter<<<(NEDGES + 255) / 256, 256>>>(src, dst);
    k_aggregate<<<(NNODES + 7) / 8, 256>>>(out);
}

// round 5
// speedup vs baseline: 1.6581x; 1.2166x over previous
#include <cuda_runtime.h>
#include <cuda_bf16.h>
#include <cstdint>

#define NNODES 100000
#define NEDGES 1600000
#define FEATS  256
#define MAXK   32
#define NCHUNK 8             // 256 / 32
#define AP     80            // padded smem row stride (bytes) for 32 bf16
#define APB    20480         // B plane bytes: 256 rows * AP
#define APA    10240         // A plane bytes: 128 rows * AP
#define SSZ    61440         // stage: Ahi|Alo (10240 ea) + Bhi|Blo (20480 ea)
#define NSTG   3
#define SMEM_DYN 184320      // 3 stages (epilogue overlay 128*258*4=132096 fits)

// ---------------- scratch (no allocations allowed) ----------------
__device__ float           g_val[NNODES * MAXK];
__device__ unsigned char   g_col[NNODES * MAXK];
__device__ int             g_deg[NNODES];
__device__ int             g_off[NNODES + 1];
__device__ int             g_cur[NNODES];
__device__ int             g_csr[NEDGES];
__device__ int             g_is64;
__device__ int             g_bsum[128];
__device__ int             g_bpre[128];
__device__ __nv_bfloat16   g_bhi[512 * 256];   // [n 0..511][k] = W^T; n<256 self, n>=256 neigh
__device__ __nv_bfloat16   g_blo[512 * 256];

// ---------------- helpers ----------------
__device__ __forceinline__ uint32_t smem_u32(const void* p) {
    uint32_t a;
    asm("{ .reg .u64 t; cvta.to.shared.u64 t, %1; cvt.u32.u64 %0, t; }" : "=r"(a) : "l"(p));
    return a;
}
__device__ __forceinline__ void cp16(uint32_t dst, const void* src) {
    asm volatile("cp.async.cg.shared.global [%0], [%1], 16;" :: "r"(dst), "l"(src));
}
#define CP_COMMIT() asm volatile("cp.async.commit_group;" ::: "memory")
#define CP_WAIT(n)  asm volatile("cp.async.wait_group %0;" :: "n"(n) : "memory")

__device__ __forceinline__ void ldm4(uint32_t r[4], uint32_t addr) {
    asm volatile("ldmatrix.sync.aligned.m8n8.x4.shared.b16 {%0,%1,%2,%3}, [%4];"
                 : "=r"(r[0]), "=r"(r[1]), "=r"(r[2]), "=r"(r[3]) : "r"(addr));
}
__device__ __forceinline__ void mma_bf16(float* c, const uint32_t* a, const uint32_t* b) {
    asm volatile("mma.sync.aligned.m16n8k16.row.col.f32.bf16.bf16.f32 "
                 "{%0,%1,%2,%3}, {%4,%5,%6,%7}, {%8,%9}, {%0,%1,%2,%3};"
                 : "+f"(c[0]), "+f"(c[1]), "+f"(c[2]), "+f"(c[3])
                 : "r"(a[0]), "r"(a[1]), "r"(a[2]), "r"(a[3]), "r"(b[0]), "r"(b[1]));
}
__device__ __forceinline__ uint32_t pack2(float x, float y) {
    uint32_t lo = (uint32_t)__bfloat16_as_ushort(__float2bfloat16_rn(x));
    uint32_t hi = (uint32_t)__bfloat16_as_ushort(__float2bfloat16_rn(y));
    return lo | (hi << 16);
}

// ---------------- dtype detection for src/dst ----------------
__global__ void k_detect(const void* src) {
    if (threadIdx.x == 0 && blockIdx.x == 0) {
        const long long* p = (const long long*)src;
        int ok = 1;
        for (int i = 0; i < 64; i++) {
            long long v = p[i];
            if (v < 0 || v >= NNODES) { ok = 0; break; }
        }
        g_is64 = ok;
    }
}
__device__ __forceinline__ int ld_idx(const void* p, int i) {
    if (g_is64) return (int)((const long long*)p)[i];
    return ((const int*)p)[i];
}

// ---------------- weight prep: W^T + bf16 hi/lo split ----------------
__global__ void k_prep_w(const float* __restrict__ Ws, const float* __restrict__ Wn) {
    int i = blockIdx.x * 256 + threadIdx.x;   // i = n*256 + k
    if (i >= 512 * 256) return;
    int k = i & 255;
    int n = i >> 8;
    float x = (n >= 256) ? Wn[k * 256 + (n - 256)] : Ws[k * 256 + n];
    __nv_bfloat16 h = __float2bfloat16_rn(x);
    float l = x - __bfloat162float(h);
    g_bhi[i] = h;
    g_blo[i] = __float2bfloat16_rn(l);
}

// ---------------- init / degree / scan / scatter ----------------
__global__ void k_zero_deg() {
    int i = blockIdx.x * blockDim.x + threadIdx.x;
    if (i < NNODES) g_deg[i] = 0;
}
__global__ void k_count(const void* dst) {
    int e = blockIdx.x * blockDim.x + threadIdx.x;
    if (e < NEDGES) atomicAdd(&g_deg[ld_idx(dst, e)], 1);
}
__global__ void k_scan1() {
    __shared__ int sh[1024];
    int t = threadIdx.x;
    int i = blockIdx.x * 1024 + t;
    int v = (i < NNODES) ? g_deg[i] : 0;
    sh[t] = v; __syncthreads();
    for (int off = 1; off < 1024; off <<= 1) {
        int x = (t >= off) ? sh[t - off] : 0;
        __syncthreads();
        sh[t] += x;
        __syncthreads();
    }
    if (i < NNODES) g_off[i] = sh[t] - v;
    if (t == 1023) g_bsum[blockIdx.x] = sh[1023];
}
__global__ void k_scan2() {
    __shared__ int sh[128];
    int t = threadIdx.x;
    int v = (t < 98) ? g_bsum[t] : 0;
    sh[t] = v; __syncthreads();
    for (int off = 1; off < 128; off <<= 1) {
        int x = (t >= off) ? sh[t - off] : 0;
        __syncthreads();
        sh[t] += x;
        __syncthreads();
    }
    g_bpre[t] = sh[t] - v;
    if (t == 127) g_off[NNODES] = sh[127];
}
__global__ void k_scan3() {
    int i = blockIdx.x * 1024 + threadIdx.x;
    if (i < NNODES) {
        int o = g_off[i] + g_bpre[blockIdx.x];
        g_off[i] = o;
        g_cur[i] = o;
    }
}
__global__ void k_scatter(const void* src, const void* dst) {
    int e = blockIdx.x * blockDim.x + threadIdx.x;
    if (e < NEDGES) {
        int s = ld_idx(src, e);
        int d = ld_idx(dst, e);
        int pos = atomicAdd(&g_cur[d], 1);
        g_csr[pos] = s;
    }
}

// ---------------- fused GEMM (+topk for neigh): C[128 x 256] per CTA ----------------
// grid (782, 2): y=0 -> h_self -> out; y=1 -> h_neigh -> in-place top-32.
// 512 threads / 16 warps: warpM = w&3 (32 rows), warpN = w>>2 (64 cols).
// 3-term bf16 compensation; A converted fp32->bf16 hi/lo in-kernel; 3-stage cp.async.
__global__ __launch_bounds__(512, 1) void k_gemm(const float* __restrict__ feat,
                                                 float* __restrict__ out) {
    extern __shared__ char sm[];
    uint32_t sb = smem_u32(sm);
    int t = threadIdx.x, lane = t & 31, w = t >> 5;
    int m = blockIdx.y;
    int rowBase = blockIdx.x * 128;
    int warpM = w & 3, warpN = w >> 2;

    // A conversion mapping: row = t>>2 (0..127), seg = t&3 (8 cols)
    int ar = t >> 2;
    int seg = t & 3;
    int grA = rowBase + ar;
    bool aOK = grA < NNODES;
    const float* aRow = feat + (size_t)grA * FEATS + seg * 8;
    float aR[8];

    auto ldA = [&](int chunk) {
        float4 v0 = aOK ? *(const float4*)(aRow + chunk * 32)     : make_float4(0.f,0.f,0.f,0.f);
        float4 v1 = aOK ? *(const float4*)(aRow + chunk * 32 + 4) : make_float4(0.f,0.f,0.f,0.f);
        aR[0]=v0.x; aR[1]=v0.y; aR[2]=v0.z; aR[3]=v0.w;
        aR[4]=v1.x; aR[5]=v1.y; aR[6]=v1.z; aR[7]=v1.w;
    };
    auto stA = [&](int stage) {
        uint32_t stOff = stage * SSZ;
        float hs[8];
#pragma unroll
        for (int q = 0; q < 8; q++) hs[q] = __bfloat162float(__float2bfloat16_rn(aR[q]));
        uint32_t h0 = pack2(hs[0], hs[1]), h1 = pack2(hs[2], hs[3]);
        uint32_t h2 = pack2(hs[4], hs[5]), h3 = pack2(hs[6], hs[7]);
        uint32_t l0 = pack2(aR[0]-hs[0], aR[1]-hs[1]), l1 = pack2(aR[2]-hs[2], aR[3]-hs[3]);
        uint32_t l2 = pack2(aR[4]-hs[4], aR[5]-hs[5]), l3 = pack2(aR[6]-hs[6], aR[7]-hs[7]);
        uint32_t dof = (uint32_t)(ar * AP + seg * 16);
        *(uint4*)(sm + stOff + dof)       = make_uint4(h0, h1, h2, h3);
        *(uint4*)(sm + stOff + APA + dof) = make_uint4(l0, l1, l2, l3);
    };
    auto cpB = [&](int stage, int chunk) {
        uint32_t bh = sb + stage * SSZ + 2 * APA;
        uint32_t bl = bh + APB;
        int kc = chunk * 32;
#pragma unroll
        for (int i = 0; i < 2; i++) {
            int lin = t + i * 512;          // 0..1023: row = lin>>2, seg = lin&3
            int n = lin >> 2, sg = lin & 3;
            uint32_t dof = (uint32_t)(n * AP + sg * 16);
            size_t bo = (size_t)(m * 256 + n) * 256 + kc + sg * 8;
            cp16(bh + dof, &g_bhi[bo]);
            cp16(bl + dof, &g_blo[bo]);
        }
        CP_COMMIT();
    };

    float acc[2][8][4];
#pragma unroll
    for (int mf = 0; mf < 2; mf++)
#pragma unroll
        for (int nf = 0; nf < 8; nf++)
#pragma unroll
            for (int q = 0; q < 4; q++) acc[mf][nf][q] = 0.f;

    // prologue
    ldA(0); stA(0); cpB(0, 0);
    ldA(1); stA(1); cpB(1, 1);
    ldA(2);

    uint32_t aoff = (uint32_t)((lane & 7) + ((lane & 8) ? 8 : 0)) * AP + ((lane & 16) ? 16 : 0);
    uint32_t boff = (uint32_t)((lane & 7) + ((lane & 16) ? 8 : 0)) * AP + ((lane & 8) ? 16 : 0);

    for (int c = 0; c < NCHUNK; c++) {
        CP_WAIT(1);
        __syncthreads();

        if (c + 2 < NCHUNK) {
            stA((c + 2) % NSTG);
            cpB((c + 2) % NSTG, c + 2);
            if (c + 3 < NCHUNK) ldA(c + 3);
        }

        uint32_t st = sb + (c % NSTG) * SSZ;
#pragma unroll
        for (int ks = 0; ks < 2; ks++) {
            uint32_t ahf[2][4], alf[2][4];
#pragma unroll
            for (int mf = 0; mf < 2; mf++) {
                uint32_t ra = st + (uint32_t)(warpM * 32 + mf * 16) * AP + aoff + ks * 32;
                ldm4(ahf[mf], ra);
                ldm4(alf[mf], ra + APA);
            }
#pragma unroll
            for (int p = 0; p < 4; p++) {
                uint32_t rbn = st + 2 * APA + (uint32_t)(warpN * 64 + p * 16) * AP + boff + ks * 32;
                uint32_t rh[4], rl[4];
                ldm4(rh, rbn);
                ldm4(rl, rbn + APB);
                uint32_t bh0[2] = { rh[0], rh[1] }, bh1[2] = { rh[2], rh[3] };
                uint32_t bl0[2] = { rl[0], rl[1] }, bl1[2] = { rl[2], rl[3] };
#pragma unroll
                for (int mf = 0; mf < 2; mf++) {
                    mma_bf16(acc[mf][2*p],   ahf[mf], bh0);
                    mma_bf16(acc[mf][2*p],   ahf[mf], bl0);
                    mma_bf16(acc[mf][2*p],   alf[mf], bh0);
                    mma_bf16(acc[mf][2*p+1], ahf[mf], bh1);
                    mma_bf16(acc[mf][2*p+1], ahf[mf], bl1);
                    mma_bf16(acc[mf][2*p+1], alf[mf], bh1);
                }
            }
        }
    }
    CP_WAIT(0);

    int g = lane >> 2, tt = lane & 3;
    if (m == 0) {
        // h_self straight to out
#pragma unroll
        for (int mf = 0; mf < 2; mf++)
#pragma unroll
            for (int nf = 0; nf < 8; nf++) {
                int r0 = rowBase + warpM * 32 + mf * 16 + g;
                int col = warpN * 64 + nf * 8 + tt * 2;
                if (r0 < NNODES)
                    *(float2*)&out[(size_t)r0 * 256 + col] = make_float2(acc[mf][nf][0], acc[mf][nf][1]);
                if (r0 + 8 < NNODES)
                    *(float2*)&out[(size_t)(r0 + 8) * 256 + col] = make_float2(acc[mf][nf][2], acc[mf][nf][3]);
            }
        return;
    }

    // h_neigh: stage into smem overlay, then in-CTA warp top-32
    __syncthreads();
    float* stg = (float*)sm;                 // 128 rows x stride 258 floats
#pragma unroll
    for (int mf = 0; mf < 2; mf++)
#pragma unroll
        for (int nf = 0; nf < 8; nf++) {
            int lr = warpM * 32 + mf * 16 + g;
            int col = warpN * 64 + nf * 8 + tt * 2;
            *(float2*)&stg[(size_t)lr * 258 + col]       = make_float2(acc[mf][nf][0], acc[mf][nf][1]);
            *(float2*)&stg[(size_t)(lr + 8) * 258 + col] = make_float2(acc[mf][nf][2], acc[mf][nf][3]);
        }
    __syncthreads();

    for (int rr = 0; rr < 8; rr++) {
        int lr = w * 8 + rr;
        int grow = rowBase + lr;
        unsigned ck[8];
#pragma unroll
        for (int j = 0; j < 8; j++) {
            int col = j * 32 + lane;
            unsigned u = __float_as_uint(stg[(size_t)lr * 258 + col]);
            unsigned key = (u & 0x80000000u) ? ~u : (u | 0x80000000u);
            ck[j] = (key & 0xFFFFFF00u) | (255u - (unsigned)col);
        }
        unsigned win = 0;
        for (int it = 0; it < MAXK; it++) {
            unsigned mx = ck[0];
#pragma unroll
            for (int j = 1; j < 8; j++) mx = (ck[j] > mx) ? ck[j] : mx;
#pragma unroll
            for (int off = 16; off > 0; off >>= 1) {
                unsigned o = __shfl_xor_sync(0xFFFFFFFFu, mx, off);
                mx = (o > mx) ? o : mx;
            }
            if (lane == it) win = mx;
#pragma unroll
            for (int j = 0; j < 8; j++) if (ck[j] == mx) ck[j] = 0;
        }
        if (grow < NNODES) {
            int col = 255 - (int)(win & 0xFFu);
            g_val[(size_t)grow * MAXK + lane] = stg[(size_t)lr * 258 + col];  // exact
            g_col[(size_t)grow * MAXK + lane] = (unsigned char)col;
        }
    }
}

// ---------------- aggregation: one warp per dst node ----------------
__global__ __launch_bounds__(256) void k_aggregate(float* __restrict__ out) {
    __shared__ float acc[8][256];
    int w = threadIdx.x >> 5;
    int lane = threadIdx.x & 31;
    int v = blockIdx.x * 8 + w;
    if (v >= NNODES) return;

#pragma unroll
    for (int j = 0; j < 8; j++) acc[w][lane + 32 * j] = 0.f;
    __syncwarp();

    int beg = g_off[v];
    int end = g_off[v + 1];
    for (int e = beg; e < end; e++) {
        int s = g_csr[e];
        int c = (int)g_col[(size_t)s * MAXK + lane];
        float val = g_val[(size_t)s * MAXK + lane];
        atomicAdd(&acc[w][c], val);
    }
    __syncwarp();

    int deg = end - beg;
    float inv = 1.0f / (float)(deg > 0 ? deg : 1);
    size_t bo = (size_t)v * FEATS;
#pragma unroll
    for (int j = 0; j < 8; j++) {
        int c = lane + 32 * j;
        out[bo + c] += acc[w][c] * inv;
    }
}

// ---------------- launch (k_gemm is the 4th launch -> gets profiled) ----------------
extern "C" void kernel_launch(void* const* d_in, const int* in_sizes, int n_in,
                              void* d_out, int out_size) {
    const float* feat = (const float*)d_in[0];
    const float* Ws   = (const float*)d_in[1];
    const float* Wn   = (const float*)d_in[2];
    const void*  src  = d_in[3];
    const void*  dst  = d_in[4];
    float* out = (float*)d_out;

    cudaFuncSetAttribute(k_gemm, cudaFuncAttributeMaxDynamicSharedMemorySize, SMEM_DYN);

    k_prep_w<<<512, 256>>>(Ws, Wn);
    k_detect<<<1, 64>>>(src);
    k_zero_deg<<<(NNODES + 255) / 256, 256>>>();
    dim3 gg(782, 2);
    k_gemm<<<gg, 512, SMEM_DYN>>>(feat, out);     // 4th launch
    k_count<<<(NEDGES + 255) / 256, 256>>>(dst);
    k_scan1<<<98, 1024>>>();
    k_scan2<<<1, 128>>>();
    k_scan3<<<98, 1024>>>();
    k_scatter<<<(NEDGES + 255) / 256, 256>>>(src, dst);
    k_aggregate<<<(NNODES + 7) / 8, 256>>>(out);
}

// round 6
// speedup vs baseline: 1.8488x; 1.1150x over previous
#include <cuda_runtime.h>
#include <cuda_bf16.h>
#include <cstdint>

#define NNODES 100000
#define NEDGES 1600000
#define FEATS  256
#define MAXK   32
#define NCHUNK 8             // 256 / 32
#define AP     80            // padded smem row stride (bytes) for 32 bf16
#define APB    20480         // B plane bytes: 256 rows * AP
#define APA    10240         // A plane bytes: 128 rows * AP
#define SSZ    61440         // stage: Ahi|Alo (10240 ea) + Bhi|Blo (20480 ea)
#define NSTG   3
#define SMEM_DYN 184320      // 3 stages (epilogue overlay 128*258*4=132096 fits)

// ---------------- scratch (no allocations allowed) ----------------
__device__ float           g_val[NNODES * MAXK];
__device__ unsigned char   g_col[NNODES * MAXK];
__device__ int             g_deg[NNODES];
__device__ int             g_off[NNODES + 1];
__device__ int             g_cur[NNODES];
__device__ int             g_csr[NEDGES];
__device__ int             g_is64;
__device__ int             g_bsum[128];
__device__ int             g_bpre[128];
__device__ __nv_bfloat16   g_bhi[512 * 256];   // [n 0..511][k] = W^T; n<256 self, n>=256 neigh
__device__ __nv_bfloat16   g_blo[512 * 256];

// ---------------- helpers ----------------
__device__ __forceinline__ uint32_t smem_u32(const void* p) {
    uint32_t a;
    asm("{ .reg .u64 t; cvta.to.shared.u64 t, %1; cvt.u32.u64 %0, t; }" : "=r"(a) : "l"(p));
    return a;
}
__device__ __forceinline__ void cp16(uint32_t dst, const void* src) {
    asm volatile("cp.async.cg.shared.global [%0], [%1], 16;" :: "r"(dst), "l"(src));
}
#define CP_COMMIT() asm volatile("cp.async.commit_group;" ::: "memory")
#define CP_WAIT(n)  asm volatile("cp.async.wait_group %0;" :: "n"(n) : "memory")

__device__ __forceinline__ void ldm4(uint32_t r[4], uint32_t addr) {
    asm volatile("ldmatrix.sync.aligned.m8n8.x4.shared.b16 {%0,%1,%2,%3}, [%4];"
                 : "=r"(r[0]), "=r"(r[1]), "=r"(r[2]), "=r"(r[3]) : "r"(addr));
}
__device__ __forceinline__ void mma_bf16(float* c, const uint32_t* a, const uint32_t* b) {
    asm volatile("mma.sync.aligned.m16n8k16.row.col.f32.bf16.bf16.f32 "
                 "{%0,%1,%2,%3}, {%4,%5,%6,%7}, {%8,%9}, {%0,%1,%2,%3};"
                 : "+f"(c[0]), "+f"(c[1]), "+f"(c[2]), "+f"(c[3])
                 : "r"(a[0]), "r"(a[1]), "r"(a[2]), "r"(a[3]), "r"(b[0]), "r"(b[1]));
}
__device__ __forceinline__ uint32_t pack2(float x, float y) {
    uint32_t lo = (uint32_t)__bfloat16_as_ushort(__float2bfloat16_rn(x));
    uint32_t hi = (uint32_t)__bfloat16_as_ushort(__float2bfloat16_rn(y));
    return lo | (hi << 16);
}
__device__ __forceinline__ unsigned max8(const unsigned* ck) {
    unsigned a = ck[0] > ck[1] ? ck[0] : ck[1];
    unsigned b = ck[2] > ck[3] ? ck[2] : ck[3];
    unsigned c = ck[4] > ck[5] ? ck[4] : ck[5];
    unsigned d = ck[6] > ck[7] ? ck[6] : ck[7];
    a = a > b ? a : b;
    c = c > d ? c : d;
    return a > c ? a : c;
}

// ---------------- dtype detection for src/dst ----------------
__global__ void k_detect(const void* src) {
    if (threadIdx.x == 0 && blockIdx.x == 0) {
        const long long* p = (const long long*)src;
        int ok = 1;
        for (int i = 0; i < 64; i++) {
            long long v = p[i];
            if (v < 0 || v >= NNODES) { ok = 0; break; }
        }
        g_is64 = ok;
    }
}
__device__ __forceinline__ int ld_idx(const void* p, int i) {
    if (g_is64) return (int)((const long long*)p)[i];
    return ((const int*)p)[i];
}

// ---------------- weight prep: W^T + bf16 hi/lo split ----------------
__global__ void k_prep_w(const float* __restrict__ Ws, const float* __restrict__ Wn) {
    int i = blockIdx.x * 256 + threadIdx.x;   // i = n*256 + k
    if (i >= 512 * 256) return;
    int k = i & 255;
    int n = i >> 8;
    float x = (n >= 256) ? Wn[k * 256 + (n - 256)] : Ws[k * 256 + n];
    __nv_bfloat16 h = __float2bfloat16_rn(x);
    float l = x - __bfloat162float(h);
    g_bhi[i] = h;
    g_blo[i] = __float2bfloat16_rn(l);
}

// ---------------- init / degree / scan / scatter ----------------
__global__ void k_zero_deg() {
    int i = blockIdx.x * blockDim.x + threadIdx.x;
    if (i < NNODES) g_deg[i] = 0;
}
__global__ void k_count(const void* dst) {
    int e = blockIdx.x * blockDim.x + threadIdx.x;
    if (e < NEDGES) atomicAdd(&g_deg[ld_idx(dst, e)], 1);
}
__global__ void k_scan1() {
    __shared__ int sh[1024];
    int t = threadIdx.x;
    int i = blockIdx.x * 1024 + t;
    int v = (i < NNODES) ? g_deg[i] : 0;
    sh[t] = v; __syncthreads();
    for (int off = 1; off < 1024; off <<= 1) {
        int x = (t >= off) ? sh[t - off] : 0;
        __syncthreads();
        sh[t] += x;
        __syncthreads();
    }
    if (i < NNODES) g_off[i] = sh[t] - v;
    if (t == 1023) g_bsum[blockIdx.x] = sh[1023];
}
__global__ void k_scan2() {
    __shared__ int sh[128];
    int t = threadIdx.x;
    int v = (t < 98) ? g_bsum[t] : 0;
    sh[t] = v; __syncthreads();
    for (int off = 1; off < 128; off <<= 1) {
        int x = (t >= off) ? sh[t - off] : 0;
        __syncthreads();
        sh[t] += x;
        __syncthreads();
    }
    g_bpre[t] = sh[t] - v;
    if (t == 127) g_off[NNODES] = sh[127];
}
__global__ void k_scan3() {
    int i = blockIdx.x * 1024 + threadIdx.x;
    if (i < NNODES) {
        int o = g_off[i] + g_bpre[blockIdx.x];
        g_off[i] = o;
        g_cur[i] = o;
    }
}
__global__ void k_scatter(const void* src, const void* dst) {
    int e = blockIdx.x * blockDim.x + threadIdx.x;
    if (e < NEDGES) {
        int s = ld_idx(src, e);
        int d = ld_idx(dst, e);
        int pos = atomicAdd(&g_cur[d], 1);
        g_csr[pos] = s;
    }
}

// ---------------- fused GEMM (+topk for neigh): C[128 x 256] per CTA ----------------
// grid (782, 2): y=0 -> h_self -> out; y=1 -> h_neigh -> in-place top-32.
// 512 threads / 16 warps: warpM = w&3 (32 rows), warpN = w>>2 (64 cols).
// 3-term bf16 compensation; A converted fp32->bf16 hi/lo in-kernel; 3-stage cp.async.
__global__ __launch_bounds__(512, 1) void k_gemm(const float* __restrict__ feat,
                                                 float* __restrict__ out) {
    extern __shared__ char sm[];
    uint32_t sb = smem_u32(sm);
    int t = threadIdx.x, lane = t & 31, w = t >> 5;
    int m = blockIdx.y;
    int rowBase = blockIdx.x * 128;
    int warpM = w & 3, warpN = w >> 2;

    // A conversion mapping: row = t>>2 (0..127), seg = t&3 (8 cols)
    int ar = t >> 2;
    int seg = t & 3;
    int grA = rowBase + ar;
    bool aOK = grA < NNODES;
    const float* aRow = feat + (size_t)grA * FEATS + seg * 8;
    float aR[8];

    auto ldA = [&](int chunk) {
        float4 v0 = aOK ? *(const float4*)(aRow + chunk * 32)     : make_float4(0.f,0.f,0.f,0.f);
        float4 v1 = aOK ? *(const float4*)(aRow + chunk * 32 + 4) : make_float4(0.f,0.f,0.f,0.f);
        aR[0]=v0.x; aR[1]=v0.y; aR[2]=v0.z; aR[3]=v0.w;
        aR[4]=v1.x; aR[5]=v1.y; aR[6]=v1.z; aR[7]=v1.w;
    };
    auto stA = [&](int stage) {
        uint32_t stOff = stage * SSZ;
        float hs[8];
#pragma unroll
        for (int q = 0; q < 8; q++) hs[q] = __bfloat162float(__float2bfloat16_rn(aR[q]));
        uint32_t h0 = pack2(hs[0], hs[1]), h1 = pack2(hs[2], hs[3]);
        uint32_t h2 = pack2(hs[4], hs[5]), h3 = pack2(hs[6], hs[7]);
        uint32_t l0 = pack2(aR[0]-hs[0], aR[1]-hs[1]), l1 = pack2(aR[2]-hs[2], aR[3]-hs[3]);
        uint32_t l2 = pack2(aR[4]-hs[4], aR[5]-hs[5]), l3 = pack2(aR[6]-hs[6], aR[7]-hs[7]);
        uint32_t dof = (uint32_t)(ar * AP + seg * 16);
        *(uint4*)(sm + stOff + dof)       = make_uint4(h0, h1, h2, h3);
        *(uint4*)(sm + stOff + APA + dof) = make_uint4(l0, l1, l2, l3);
    };
    auto cpB = [&](int stage, int chunk) {
        uint32_t bh = sb + stage * SSZ + 2 * APA;
        uint32_t bl = bh + APB;
        int kc = chunk * 32;
#pragma unroll
        for (int i = 0; i < 2; i++) {
            int lin = t + i * 512;          // 0..1023: row = lin>>2, seg = lin&3
            int n = lin >> 2, sg = lin & 3;
            uint32_t dof = (uint32_t)(n * AP + sg * 16);
            size_t bo = (size_t)(m * 256 + n) * 256 + kc + sg * 8;
            cp16(bh + dof, &g_bhi[bo]);
            cp16(bl + dof, &g_blo[bo]);
        }
        CP_COMMIT();
    };

    float acc[2][8][4];
#pragma unroll
    for (int mf = 0; mf < 2; mf++)
#pragma unroll
        for (int nf = 0; nf < 8; nf++)
#pragma unroll
            for (int q = 0; q < 4; q++) acc[mf][nf][q] = 0.f;

    // prologue
    ldA(0); stA(0); cpB(0, 0);
    ldA(1); stA(1); cpB(1, 1);
    ldA(2);

    uint32_t aoff = (uint32_t)((lane & 7) + ((lane & 8) ? 8 : 0)) * AP + ((lane & 16) ? 16 : 0);
    uint32_t boff = (uint32_t)((lane & 7) + ((lane & 16) ? 8 : 0)) * AP + ((lane & 8) ? 16 : 0);

    for (int c = 0; c < NCHUNK; c++) {
        CP_WAIT(1);
        __syncthreads();

        if (c + 2 < NCHUNK) {
            stA((c + 2) % NSTG);
            cpB((c + 2) % NSTG, c + 2);
            if (c + 3 < NCHUNK) ldA(c + 3);
        }

        uint32_t st = sb + (c % NSTG) * SSZ;
#pragma unroll
        for (int ks = 0; ks < 2; ks++) {
            uint32_t ahf[2][4], alf[2][4];
#pragma unroll
            for (int mf = 0; mf < 2; mf++) {
                uint32_t ra = st + (uint32_t)(warpM * 32 + mf * 16) * AP + aoff + ks * 32;
                ldm4(ahf[mf], ra);
                ldm4(alf[mf], ra + APA);
            }
#pragma unroll
            for (int p = 0; p < 4; p++) {
                uint32_t rbn = st + 2 * APA + (uint32_t)(warpN * 64 + p * 16) * AP + boff + ks * 32;
                uint32_t rh[4], rl[4];
                ldm4(rh, rbn);
                ldm4(rl, rbn + APB);
                uint32_t bh0[2] = { rh[0], rh[1] }, bh1[2] = { rh[2], rh[3] };
                uint32_t bl0[2] = { rl[0], rl[1] }, bl1[2] = { rl[2], rl[3] };
#pragma unroll
                for (int mf = 0; mf < 2; mf++) {
                    mma_bf16(acc[mf][2*p],   ahf[mf], bh0);
                    mma_bf16(acc[mf][2*p],   ahf[mf], bl0);
                    mma_bf16(acc[mf][2*p],   alf[mf], bh0);
                    mma_bf16(acc[mf][2*p+1], ahf[mf], bh1);
                    mma_bf16(acc[mf][2*p+1], ahf[mf], bl1);
                    mma_bf16(acc[mf][2*p+1], alf[mf], bh1);
                }
            }
        }
    }
    CP_WAIT(0);

    int g = lane >> 2, tt = lane & 3;
    if (m == 0) {
        // h_self straight to out
#pragma unroll
        for (int mf = 0; mf < 2; mf++)
#pragma unroll
            for (int nf = 0; nf < 8; nf++) {
                int r0 = rowBase + warpM * 32 + mf * 16 + g;
                int col = warpN * 64 + nf * 8 + tt * 2;
                if (r0 < NNODES)
                    *(float2*)&out[(size_t)r0 * 256 + col] = make_float2(acc[mf][nf][0], acc[mf][nf][1]);
                if (r0 + 8 < NNODES)
                    *(float2*)&out[(size_t)(r0 + 8) * 256 + col] = make_float2(acc[mf][nf][2], acc[mf][nf][3]);
            }
        return;
    }

    // h_neigh: stage into smem overlay, then in-CTA top-32 (REDUX-based, 2 rows interleaved)
    __syncthreads();
    float* stg = (float*)sm;                 // 128 rows x stride 258 floats
#pragma unroll
    for (int mf = 0; mf < 2; mf++)
#pragma unroll
        for (int nf = 0; nf < 8; nf++) {
            int lr = warpM * 32 + mf * 16 + g;
            int col = warpN * 64 + nf * 8 + tt * 2;
            *(float2*)&stg[(size_t)lr * 258 + col]       = make_float2(acc[mf][nf][0], acc[mf][nf][1]);
            *(float2*)&stg[(size_t)(lr + 8) * 258 + col] = make_float2(acc[mf][nf][2], acc[mf][nf][3]);
        }
    __syncthreads();

    for (int rp = 0; rp < 4; rp++) {
        int lrA = w * 8 + rp * 2;
        int lrB = lrA + 1;
        unsigned ckA[8], ckB[8];
#pragma unroll
        for (int j = 0; j < 8; j++) {
            int col = j * 32 + lane;
            unsigned uA = __float_as_uint(stg[(size_t)lrA * 258 + col]);
            unsigned kA = (uA & 0x80000000u) ? ~uA : (uA | 0x80000000u);
            ckA[j] = (kA & 0xFFFFFF00u) | (255u - (unsigned)col);
            unsigned uB = __float_as_uint(stg[(size_t)lrB * 258 + col]);
            unsigned kB = (uB & 0x80000000u) ? ~uB : (uB | 0x80000000u);
            ckB[j] = (kB & 0xFFFFFF00u) | (255u - (unsigned)col);
        }
        unsigned lmaxA = max8(ckA);
        unsigned lmaxB = max8(ckB);
        unsigned winA = 0, winB = 0;
#pragma unroll
        for (int it = 0; it < MAXK; it++) {
            unsigned gA = __reduce_max_sync(0xFFFFFFFFu, lmaxA);
            unsigned gB = __reduce_max_sync(0xFFFFFFFFu, lmaxB);
            if (lane == it) { winA = gA; winB = gB; }
            if (lmaxA == gA) {
#pragma unroll
                for (int j = 0; j < 8; j++) if (ckA[j] == gA) ckA[j] = 0;
                lmaxA = max8(ckA);
            }
            if (lmaxB == gB) {
#pragma unroll
                for (int j = 0; j < 8; j++) if (ckB[j] == gB) ckB[j] = 0;
                lmaxB = max8(ckB);
            }
        }
        int growA = rowBase + lrA;
        int growB = rowBase + lrB;
        if (growA < NNODES) {
            int col = 255 - (int)(winA & 0xFFu);
            g_val[(size_t)growA * MAXK + lane] = stg[(size_t)lrA * 258 + col];  // exact
            g_col[(size_t)growA * MAXK + lane] = (unsigned char)col;
        }
        if (growB < NNODES) {
            int col = 255 - (int)(winB & 0xFFu);
            g_val[(size_t)growB * MAXK + lane] = stg[(size_t)lrB * 258 + col];
            g_col[(size_t)growB * MAXK + lane] = (unsigned char)col;
        }
    }
}

// ---------------- aggregation: one warp per dst node ----------------
__global__ __launch_bounds__(256) void k_aggregate(float* __restrict__ out) {
    __shared__ float acc[8][256];
    int w = threadIdx.x >> 5;
    int lane = threadIdx.x & 31;
    int v = blockIdx.x * 8 + w;
    if (v >= NNODES) return;

#pragma unroll
    for (int j = 0; j < 8; j++) acc[w][lane + 32 * j] = 0.f;
    __syncwarp();

    int beg = g_off[v];
    int end = g_off[v + 1];
    for (int e = beg; e < end; e++) {
        int s = g_csr[e];
        int c = (int)g_col[(size_t)s * MAXK + lane];
        float val = g_val[(size_t)s * MAXK + lane];
        atomicAdd(&acc[w][c], val);
    }
    __syncwarp();

    int deg = end - beg;
    float inv = 1.0f / (float)(deg > 0 ? deg : 1);
    size_t bo = (size_t)v * FEATS;
#pragma unroll
    for (int j = 0; j < 8; j++) {
        int c = lane + 32 * j;
        out[bo + c] += acc[w][c] * inv;
    }
}

// ---------------- launch (k_gemm is the 4th launch -> gets profiled) ----------------
extern "C" void kernel_launch(void* const* d_in, const int* in_sizes, int n_in,
                              void* d_out, int out_size) {
    const float* feat = (const float*)d_in[0];
    const float* Ws   = (const float*)d_in[1];
    const float* Wn   = (const float*)d_in[2];
    const void*  src  = d_in[3];
    const void*  dst  = d_in[4];
    float* out = (float*)d_out;

    cudaFuncSetAttribute(k_gemm, cudaFuncAttributeMaxDynamicSharedMemorySize, SMEM_DYN);

    k_prep_w<<<512, 256>>>(Ws, Wn);
    k_detect<<<1, 64>>>(src);
    k_zero_deg<<<(NNODES + 255) / 256, 256>>>();
    dim3 gg(782, 2);
    k_gemm<<<gg, 512, SMEM_DYN>>>(feat, out);     // 4th launch
    k_count<<<(NEDGES + 255) / 256, 256>>>(dst);
    k_scan1<<<98, 1024>>>();
    k_scan2<<<1, 128>>>();
    k_scan3<<<98, 1024>>>();
    k_scatter<<<(NEDGES + 255) / 256, 256>>>(src, dst);
    k_aggregate<<<(NNODES + 7) / 8, 256>>>(out);
}

// round 7
// speedup vs baseline: 1.8492x; 1.0002x over previous
#include <cuda_runtime.h>
#include <cuda_bf16.h>
#include <cstdint>

#define NNODES 100000
#define NEDGES 1600000
#define FEATS  256
#define MAXK   32
#define NCHUNK 8             // 256 / 32
#define AP     80            // padded smem row stride (bytes) for 32 bf16
#define APB    20480         // B plane bytes: 256 rows * AP
#define APA    10240         // A plane bytes: 128 rows * AP
#define SSZ    61440         // stage: Ahi|Alo (10240 ea) + Bhi|Blo (20480 ea)
#define NSTG   3
#define SMEM_DYN 184320      // 3 stages (epilogue overlay 128*258*4=132096 fits)

// ---------------- scratch (no allocations allowed) ----------------
__device__ float           g_val[NNODES * MAXK];
__device__ unsigned char   g_col[NNODES * MAXK];
__device__ int             g_deg[NNODES];
__device__ int             g_off[NNODES + 1];
__device__ int             g_cur[NNODES];
__device__ int             g_csr[NEDGES];
__device__ int             g_is64;
__device__ int             g_bsum[128];
__device__ int             g_bpre[128];
__device__ __nv_bfloat16   g_bhi[512 * 256];   // [n 0..511][k] = W^T; n<256 self, n>=256 neigh
__device__ __nv_bfloat16   g_blo[512 * 256];

// ---------------- helpers ----------------
__device__ __forceinline__ uint32_t smem_u32(const void* p) {
    uint32_t a;
    asm("{ .reg .u64 t; cvta.to.shared.u64 t, %1; cvt.u32.u64 %0, t; }" : "=r"(a) : "l"(p));
    return a;
}
__device__ __forceinline__ void cp16(uint32_t dst, const void* src) {
    asm volatile("cp.async.cg.shared.global [%0], [%1], 16;" :: "r"(dst), "l"(src));
}
#define CP_COMMIT() asm volatile("cp.async.commit_group;" ::: "memory")
#define CP_WAIT(n)  asm volatile("cp.async.wait_group %0;" :: "n"(n) : "memory")

__device__ __forceinline__ void ldm4(uint32_t r[4], uint32_t addr) {
    asm volatile("ldmatrix.sync.aligned.m8n8.x4.shared.b16 {%0,%1,%2,%3}, [%4];"
                 : "=r"(r[0]), "=r"(r[1]), "=r"(r[2]), "=r"(r[3]) : "r"(addr));
}
__device__ __forceinline__ void mma_bf16(float* c, const uint32_t* a, const uint32_t* b) {
    asm volatile("mma.sync.aligned.m16n8k16.row.col.f32.bf16.bf16.f32 "
                 "{%0,%1,%2,%3}, {%4,%5,%6,%7}, {%8,%9}, {%0,%1,%2,%3};"
                 : "+f"(c[0]), "+f"(c[1]), "+f"(c[2]), "+f"(c[3])
                 : "r"(a[0]), "r"(a[1]), "r"(a[2]), "r"(a[3]), "r"(b[0]), "r"(b[1]));
}
__device__ __forceinline__ uint32_t pack2(float x, float y) {
    uint32_t lo = (uint32_t)__bfloat16_as_ushort(__float2bfloat16_rn(x));
    uint32_t hi = (uint32_t)__bfloat16_as_ushort(__float2bfloat16_rn(y));
    return lo | (hi << 16);
}
__device__ __forceinline__ unsigned max8(const unsigned* ck) {
    unsigned a = ck[0] > ck[1] ? ck[0] : ck[1];
    unsigned b = ck[2] > ck[3] ? ck[2] : ck[3];
    unsigned c = ck[4] > ck[5] ? ck[4] : ck[5];
    unsigned d = ck[6] > ck[7] ? ck[6] : ck[7];
    a = a > b ? a : b;
    c = c > d ? c : d;
    return a > c ? a : c;
}

// ---------------- dtype detection for src/dst ----------------
__global__ void k_detect(const void* src) {
    if (threadIdx.x == 0 && blockIdx.x == 0) {
        const long long* p = (const long long*)src;
        int ok = 1;
        for (int i = 0; i < 64; i++) {
            long long v = p[i];
            if (v < 0 || v >= NNODES) { ok = 0; break; }
        }
        g_is64 = ok;
    }
}
__device__ __forceinline__ int ld_idx(const void* p, int i) {
    if (g_is64) return (int)((const long long*)p)[i];
    return ((const int*)p)[i];
}

// ---------------- weight prep: W^T + bf16 hi/lo split ----------------
__global__ void k_prep_w(const float* __restrict__ Ws, const float* __restrict__ Wn) {
    int i = blockIdx.x * 256 + threadIdx.x;   // i = n*256 + k
    if (i >= 512 * 256) return;
    int k = i & 255;
    int n = i >> 8;
    float x = (n >= 256) ? Wn[k * 256 + (n - 256)] : Ws[k * 256 + n];
    __nv_bfloat16 h = __float2bfloat16_rn(x);
    float l = x - __bfloat162float(h);
    g_bhi[i] = h;
    g_blo[i] = __float2bfloat16_rn(l);
}

// ---------------- init / degree / scan / scatter ----------------
__global__ void k_zero_deg() {
    int i = blockIdx.x * blockDim.x + threadIdx.x;
    if (i < NNODES) g_deg[i] = 0;
}
__global__ void k_count(const void* dst) {
    int e = blockIdx.x * blockDim.x + threadIdx.x;
    if (e < NEDGES) atomicAdd(&g_deg[ld_idx(dst, e)], 1);
}
__global__ void k_scan1() {
    __shared__ int sh[1024];
    int t = threadIdx.x;
    int i = blockIdx.x * 1024 + t;
    int v = (i < NNODES) ? g_deg[i] : 0;
    sh[t] = v; __syncthreads();
    for (int off = 1; off < 1024; off <<= 1) {
        int x = (t >= off) ? sh[t - off] : 0;
        __syncthreads();
        sh[t] += x;
        __syncthreads();
    }
    if (i < NNODES) g_off[i] = sh[t] - v;
    if (t == 1023) g_bsum[blockIdx.x] = sh[1023];
}
__global__ void k_scan2() {
    __shared__ int sh[128];
    int t = threadIdx.x;
    int v = (t < 98) ? g_bsum[t] : 0;
    sh[t] = v; __syncthreads();
    for (int off = 1; off < 128; off <<= 1) {
        int x = (t >= off) ? sh[t - off] : 0;
        __syncthreads();
        sh[t] += x;
        __syncthreads();
    }
    g_bpre[t] = sh[t] - v;
    if (t == 127) g_off[NNODES] = sh[127];
}
__global__ void k_scan3() {
    int i = blockIdx.x * 1024 + threadIdx.x;
    if (i < NNODES) {
        int o = g_off[i] + g_bpre[blockIdx.x];
        g_off[i] = o;
        g_cur[i] = o;
    }
}
__global__ void k_scatter(const void* src, const void* dst) {
    int e = blockIdx.x * blockDim.x + threadIdx.x;
    if (e < NEDGES) {
        int s = ld_idx(src, e);
        int d = ld_idx(dst, e);
        int pos = atomicAdd(&g_cur[d], 1);
        g_csr[pos] = s;
    }
}

// ---------------- fused GEMM (+topk for neigh): C[128 x 256] per CTA ----------------
// grid (782, 2): y=0 -> h_self -> out; y=1 -> h_neigh -> in-place top-32.
// 512 threads / 16 warps: warpM = w&3 (32 rows), warpN = w>>2 (64 cols).
// 3-term bf16 compensation; MMA issue order round-robins 4 accumulators (no RAW stalls).
__global__ __launch_bounds__(512, 1) void k_gemm(const float* __restrict__ feat,
                                                 float* __restrict__ out) {
    extern __shared__ char sm[];
    uint32_t sb = smem_u32(sm);
    int t = threadIdx.x, lane = t & 31, w = t >> 5;
    int m = blockIdx.y;
    int rowBase = blockIdx.x * 128;
    int warpM = w & 3, warpN = w >> 2;

    // A conversion mapping: row = t>>2 (0..127), seg = t&3 (8 cols)
    int ar = t >> 2;
    int seg = t & 3;
    int grA = rowBase + ar;
    bool aOK = grA < NNODES;
    const float* aRow = feat + (size_t)grA * FEATS + seg * 8;
    float aR[8];

    auto ldA = [&](int chunk) {
        float4 v0 = aOK ? *(const float4*)(aRow + chunk * 32)     : make_float4(0.f,0.f,0.f,0.f);
        float4 v1 = aOK ? *(const float4*)(aRow + chunk * 32 + 4) : make_float4(0.f,0.f,0.f,0.f);
        aR[0]=v0.x; aR[1]=v0.y; aR[2]=v0.z; aR[3]=v0.w;
        aR[4]=v1.x; aR[5]=v1.y; aR[6]=v1.z; aR[7]=v1.w;
    };
    auto stA = [&](int stage) {
        uint32_t stOff = stage * SSZ;
        float hs[8];
#pragma unroll
        for (int q = 0; q < 8; q++) hs[q] = __bfloat162float(__float2bfloat16_rn(aR[q]));
        uint32_t h0 = pack2(hs[0], hs[1]), h1 = pack2(hs[2], hs[3]);
        uint32_t h2 = pack2(hs[4], hs[5]), h3 = pack2(hs[6], hs[7]);
        uint32_t l0 = pack2(aR[0]-hs[0], aR[1]-hs[1]), l1 = pack2(aR[2]-hs[2], aR[3]-hs[3]);
        uint32_t l2 = pack2(aR[4]-hs[4], aR[5]-hs[5]), l3 = pack2(aR[6]-hs[6], aR[7]-hs[7]);
        uint32_t dof = (uint32_t)(ar * AP + seg * 16);
        *(uint4*)(sm + stOff + dof)       = make_uint4(h0, h1, h2, h3);
        *(uint4*)(sm + stOff + APA + dof) = make_uint4(l0, l1, l2, l3);
    };
    auto cpB = [&](int stage, int chunk) {
        uint32_t bh = sb + stage * SSZ + 2 * APA;
        uint32_t bl = bh + APB;
        int kc = chunk * 32;
#pragma unroll
        for (int i = 0; i < 2; i++) {
            int lin = t + i * 512;          // 0..1023: row = lin>>2, seg = lin&3
            int n = lin >> 2, sg = lin & 3;
            uint32_t dof = (uint32_t)(n * AP + sg * 16);
            size_t bo = (size_t)(m * 256 + n) * 256 + kc + sg * 8;
            cp16(bh + dof, &g_bhi[bo]);
            cp16(bl + dof, &g_blo[bo]);
        }
        CP_COMMIT();
    };

    float acc[2][8][4];
#pragma unroll
    for (int mf = 0; mf < 2; mf++)
#pragma unroll
        for (int nf = 0; nf < 8; nf++)
#pragma unroll
            for (int q = 0; q < 4; q++) acc[mf][nf][q] = 0.f;

    // prologue
    ldA(0); stA(0); cpB(0, 0);
    ldA(1); stA(1); cpB(1, 1);
    ldA(2);

    uint32_t aoff = (uint32_t)((lane & 7) + ((lane & 8) ? 8 : 0)) * AP + ((lane & 16) ? 16 : 0);
    uint32_t boff = (uint32_t)((lane & 7) + ((lane & 16) ? 8 : 0)) * AP + ((lane & 8) ? 16 : 0);

    int scC = 0, scF = 2;                    // compute / fill stage counters (no % in loop)
    for (int c = 0; c < NCHUNK; c++) {
        CP_WAIT(1);
        __syncthreads();

        if (c + 2 < NCHUNK) {
            stA(scF);
            cpB(scF, c + 2);
            if (c + 3 < NCHUNK) ldA(c + 3);
        }

        uint32_t st = sb + scC * SSZ;
#pragma unroll
        for (int ks = 0; ks < 2; ks++) {
            uint32_t ahf[2][4], alf[2][4];
#pragma unroll
            for (int mf = 0; mf < 2; mf++) {
                uint32_t ra = st + (uint32_t)(warpM * 32 + mf * 16) * AP + aoff + ks * 32;
                ldm4(ahf[mf], ra);
                ldm4(alf[mf], ra + APA);
            }
#pragma unroll
            for (int p = 0; p < 4; p++) {
                uint32_t rbn = st + 2 * APA + (uint32_t)(warpN * 64 + p * 16) * AP + boff + ks * 32;
                uint32_t rh[4], rl[4];
                ldm4(rh, rbn);
                ldm4(rl, rbn + APB);
                uint32_t bh0[2] = { rh[0], rh[1] }, bh1[2] = { rh[2], rh[3] };
                uint32_t bl0[2] = { rl[0], rl[1] }, bl1[2] = { rl[2], rl[3] };
                // term-major, round-robin over 4 accumulators: same-acc distance = 4
                mma_bf16(acc[0][2*p],   ahf[0], bh0);
                mma_bf16(acc[1][2*p],   ahf[1], bh0);
                mma_bf16(acc[0][2*p+1], ahf[0], bh1);
                mma_bf16(acc[1][2*p+1], ahf[1], bh1);

                mma_bf16(acc[0][2*p],   ahf[0], bl0);
                mma_bf16(acc[1][2*p],   ahf[1], bl0);
                mma_bf16(acc[0][2*p+1], ahf[0], bl1);
                mma_bf16(acc[1][2*p+1], ahf[1], bl1);

                mma_bf16(acc[0][2*p],   alf[0], bh0);
                mma_bf16(acc[1][2*p],   alf[1], bh0);
                mma_bf16(acc[0][2*p+1], alf[0], bh1);
                mma_bf16(acc[1][2*p+1], alf[1], bh1);
            }
        }
        scC = (scC == NSTG - 1) ? 0 : scC + 1;
        scF = (scF == NSTG - 1) ? 0 : scF + 1;
    }
    CP_WAIT(0);

    int g = lane >> 2, tt = lane & 3;
    if (m == 0) {
        // h_self straight to out
#pragma unroll
        for (int mf = 0; mf < 2; mf++)
#pragma unroll
            for (int nf = 0; nf < 8; nf++) {
                int r0 = rowBase + warpM * 32 + mf * 16 + g;
                int col = warpN * 64 + nf * 8 + tt * 2;
                if (r0 < NNODES)
                    *(float2*)&out[(size_t)r0 * 256 + col] = make_float2(acc[mf][nf][0], acc[mf][nf][1]);
                if (r0 + 8 < NNODES)
                    *(float2*)&out[(size_t)(r0 + 8) * 256 + col] = make_float2(acc[mf][nf][2], acc[mf][nf][3]);
            }
        return;
    }

    // h_neigh: stage into smem overlay, then top-32 with 4 interleaved REDUX chains
    __syncthreads();
    float* stg = (float*)sm;                 // 128 rows x stride 258 floats
#pragma unroll
    for (int mf = 0; mf < 2; mf++)
#pragma unroll
        for (int nf = 0; nf < 8; nf++) {
            int lr = warpM * 32 + mf * 16 + g;
            int col = warpN * 64 + nf * 8 + tt * 2;
            *(float2*)&stg[(size_t)lr * 258 + col]       = make_float2(acc[mf][nf][0], acc[mf][nf][1]);
            *(float2*)&stg[(size_t)(lr + 8) * 258 + col] = make_float2(acc[mf][nf][2], acc[mf][nf][3]);
        }
    __syncthreads();

    for (int rp = 0; rp < 2; rp++) {
        int lr0 = w * 8 + rp * 4;
        unsigned ck[4][8], lmax[4], win[4];
#pragma unroll
        for (int r = 0; r < 4; r++) {
#pragma unroll
            for (int j = 0; j < 8; j++) {
                int col = j * 32 + lane;
                unsigned u = __float_as_uint(stg[(size_t)(lr0 + r) * 258 + col]);
                unsigned key = (u & 0x80000000u) ? ~u : (u | 0x80000000u);
                ck[r][j] = (key & 0xFFFFFF00u) | (255u - (unsigned)col);
            }
            lmax[r] = max8(ck[r]);
            win[r] = 0;
        }
#pragma unroll
        for (int it = 0; it < MAXK; it++) {
            unsigned gm[4];
#pragma unroll
            for (int r = 0; r < 4; r++) gm[r] = __reduce_max_sync(0xFFFFFFFFu, lmax[r]);
#pragma unroll
            for (int r = 0; r < 4; r++) {
                if (lane == it) win[r] = gm[r];
                if (lmax[r] == gm[r]) {
#pragma unroll
                    for (int j = 0; j < 8; j++) if (ck[r][j] == gm[r]) ck[r][j] = 0;
                    lmax[r] = max8(ck[r]);
                }
            }
        }
#pragma unroll
        for (int r = 0; r < 4; r++) {
            int grow = rowBase + lr0 + r;
            if (grow < NNODES) {
                int col = 255 - (int)(win[r] & 0xFFu);
                g_val[(size_t)grow * MAXK + lane] = stg[(size_t)(lr0 + r) * 258 + col];  // exact
                g_col[(size_t)grow * MAXK + lane] = (unsigned char)col;
            }
        }
    }
}

// ---------------- aggregation: one warp per dst node ----------------
__global__ __launch_bounds__(256) void k_aggregate(float* __restrict__ out) {
    __shared__ float acc[8][256];
    int w = threadIdx.x >> 5;
    int lane = threadIdx.x & 31;
    int v = blockIdx.x * 8 + w;
    if (v >= NNODES) return;

#pragma unroll
    for (int j = 0; j < 8; j++) acc[w][lane + 32 * j] = 0.f;
    __syncwarp();

    int beg = g_off[v];
    int end = g_off[v + 1];
    for (int e = beg; e < end; e++) {
        int s = g_csr[e];
        int c = (int)g_col[(size_t)s * MAXK + lane];
        float val = g_val[(size_t)s * MAXK + lane];
        atomicAdd(&acc[w][c], val);
    }
    __syncwarp();

    int deg = end - beg;
    float inv = 1.0f / (float)(deg > 0 ? deg : 1);
    size_t bo = (size_t)v * FEATS;
#pragma unroll
    for (int j = 0; j < 8; j++) {
        int c = lane + 32 * j;
        out[bo + c] += acc[w][c] * inv;
    }
}

// ---------------- launch (k_gemm is the 4th launch -> gets profiled) ----------------
extern "C" void kernel_launch(void* const* d_in, const int* in_sizes, int n_in,
                              void* d_out, int out_size) {
    const float* feat = (const float*)d_in[0];
    const float* Ws   = (const float*)d_in[1];
    const float* Wn   = (const float*)d_in[2];
    const void*  src  = d_in[3];
    const void*  dst  = d_in[4];
    float* out = (float*)d_out;

    cudaFuncSetAttribute(k_gemm, cudaFuncAttributeMaxDynamicSharedMemorySize, SMEM_DYN);

    k_prep_w<<<512, 256>>>(Ws, Wn);
    k_detect<<<1, 64>>>(src);
    k_zero_deg<<<(NNODES + 255) / 256, 256>>>();
    dim3 gg(782, 2);
    k_gemm<<<gg, 512, SMEM_DYN>>>(feat, out);     // 4th launch
    k_count<<<(NEDGES + 255) / 256, 256>>>(dst);
    k_scan1<<<98, 1024>>>();
    k_scan2<<<1, 128>>>();
    k_scan3<<<98, 1024>>>();
    k_scatter<<<(NEDGES + 255) / 256, 256>>>(src, dst);
    k_aggregate<<<(NNODES + 7) / 8, 256>>>(out);
}